// round 1
// baseline (speedup 1.0000x reference)
#include <cuda_runtime.h>
#include <math.h>

// ---------------------------------------------------------------------------
// Problem constants (B=1)
// ---------------------------------------------------------------------------
#define T_SEQ 2048
#define D_MODEL 4096
#define KV_DIM 1024
#define HEAD_DIM 128
#define N_HEADS 32
#define N_KV_HEADS 8

// GEMM tiling
#define BM 128
#define BN 128
#define BK 16
#define TM 8
#define TN 8
#define NTHREADS 256

// ---------------------------------------------------------------------------
// Scratch (static device globals; no runtime allocation)
// ---------------------------------------------------------------------------
__device__ float g_q[T_SEQ * D_MODEL];                 // 32 MB
__device__ float g_k[T_SEQ * KV_DIM];                  // 8 MB
__device__ float g_v[T_SEQ * KV_DIM];                  // 8 MB
__device__ float g_y[T_SEQ * D_MODEL];                 // 32 MB
__device__ float g_scores[134217728];                  // 32*2048*2048 = 512 MB

// ---------------------------------------------------------------------------
// GEMM: C[M,N] = A[M,K] * B[N,K]^T   (both A and B are K-contiguous)
// grid = (N/BN, M/BM), block = 256
// ---------------------------------------------------------------------------
__global__ __launch_bounds__(NTHREADS)
void gemm_nt(const float* __restrict__ A, const float* __restrict__ B,
             float* __restrict__ C, int K, int lda, int ldb, int ldc)
{
    __shared__ __align__(16) float As[BK][BM];
    __shared__ __align__(16) float Bs[BK][BN];

    const int tid = threadIdx.x;
    const int tx = tid % 16;
    const int ty = tid / 16;

    const float* Ab = A + (size_t)blockIdx.y * BM * lda;
    const float* Bb = B + (size_t)blockIdx.x * BN * ldb;

    float acc[TM][TN];
#pragma unroll
    for (int i = 0; i < TM; ++i)
#pragma unroll
        for (int j = 0; j < TN; ++j) acc[i][j] = 0.f;

    for (int k0 = 0; k0 < K; k0 += BK) {
#pragma unroll
        for (int it = 0; it < 2; ++it) {
            int idx = tid + it * NTHREADS;        // 0..511
            int row = idx >> 2;                   // 0..127
            int c4  = idx & 3;                    // 0..3
            float4 va = *(const float4*)(Ab + (size_t)row * lda + k0 + c4 * 4);
            As[c4 * 4 + 0][row] = va.x;
            As[c4 * 4 + 1][row] = va.y;
            As[c4 * 4 + 2][row] = va.z;
            As[c4 * 4 + 3][row] = va.w;
            float4 vb = *(const float4*)(Bb + (size_t)row * ldb + k0 + c4 * 4);
            Bs[c4 * 4 + 0][row] = vb.x;
            Bs[c4 * 4 + 1][row] = vb.y;
            Bs[c4 * 4 + 2][row] = vb.z;
            Bs[c4 * 4 + 3][row] = vb.w;
        }
        __syncthreads();
#pragma unroll
        for (int k = 0; k < BK; ++k) {
            float4 a0 = *(const float4*)&As[k][ty * TM];
            float4 a1 = *(const float4*)&As[k][ty * TM + 4];
            float4 b0 = *(const float4*)&Bs[k][tx * TN];
            float4 b1 = *(const float4*)&Bs[k][tx * TN + 4];
            float a[TM] = {a0.x, a0.y, a0.z, a0.w, a1.x, a1.y, a1.z, a1.w};
            float b[TN] = {b0.x, b0.y, b0.z, b0.w, b1.x, b1.y, b1.z, b1.w};
#pragma unroll
            for (int i = 0; i < TM; ++i)
#pragma unroll
                for (int j = 0; j < TN; ++j) acc[i][j] += a[i] * b[j];
        }
        __syncthreads();
    }

    int crow0 = blockIdx.y * BM + ty * TM;
    int ccol0 = blockIdx.x * BN + tx * TN;
#pragma unroll
    for (int i = 0; i < TM; ++i)
#pragma unroll
        for (int j = 0; j < TN; ++j)
            C[(size_t)(crow0 + i) * ldc + ccol0 + j] = acc[i][j];
}

// ---------------------------------------------------------------------------
// Batched scores: S[h][q][k] = scale * Q[h] . K[h/4], causal block skip
// grid = (T/BN, T/BM, N_HEADS)
// ---------------------------------------------------------------------------
__global__ __launch_bounds__(NTHREADS)
void gemm_scores(const float* __restrict__ Q, const float* __restrict__ Kt,
                 float* __restrict__ S, float scale)
{
    const int h = blockIdx.z;
    const int q0 = blockIdx.y * BM;
    const int c0 = blockIdx.x * BN;
    if (c0 > q0 + BM - 1) return;   // block fully above the causal diagonal

    const float* A = Q + (size_t)h * HEAD_DIM;            // lda = D_MODEL
    const float* B = Kt + (size_t)(h >> 2) * HEAD_DIM;    // ldb = KV_DIM
    float* C = S + (size_t)h * T_SEQ * T_SEQ;

    __shared__ __align__(16) float As[BK][BM];
    __shared__ __align__(16) float Bs[BK][BN];

    const int tid = threadIdx.x;
    const int tx = tid % 16;
    const int ty = tid / 16;

    const float* Ab = A + (size_t)q0 * D_MODEL;
    const float* Bb = B + (size_t)c0 * KV_DIM;

    float acc[TM][TN];
#pragma unroll
    for (int i = 0; i < TM; ++i)
#pragma unroll
        for (int j = 0; j < TN; ++j) acc[i][j] = 0.f;

    for (int k0 = 0; k0 < HEAD_DIM; k0 += BK) {
#pragma unroll
        for (int it = 0; it < 2; ++it) {
            int idx = tid + it * NTHREADS;
            int row = idx >> 2;
            int c4  = idx & 3;
            float4 va = *(const float4*)(Ab + (size_t)row * D_MODEL + k0 + c4 * 4);
            As[c4 * 4 + 0][row] = va.x;
            As[c4 * 4 + 1][row] = va.y;
            As[c4 * 4 + 2][row] = va.z;
            As[c4 * 4 + 3][row] = va.w;
            float4 vb = *(const float4*)(Bb + (size_t)row * KV_DIM + k0 + c4 * 4);
            Bs[c4 * 4 + 0][row] = vb.x;
            Bs[c4 * 4 + 1][row] = vb.y;
            Bs[c4 * 4 + 2][row] = vb.z;
            Bs[c4 * 4 + 3][row] = vb.w;
        }
        __syncthreads();
#pragma unroll
        for (int k = 0; k < BK; ++k) {
            float4 a0 = *(const float4*)&As[k][ty * TM];
            float4 a1 = *(const float4*)&As[k][ty * TM + 4];
            float4 b0 = *(const float4*)&Bs[k][tx * TN];
            float4 b1 = *(const float4*)&Bs[k][tx * TN + 4];
            float a[TM] = {a0.x, a0.y, a0.z, a0.w, a1.x, a1.y, a1.z, a1.w};
            float b[TN] = {b0.x, b0.y, b0.z, b0.w, b1.x, b1.y, b1.z, b1.w};
#pragma unroll
            for (int i = 0; i < TM; ++i)
#pragma unroll
                for (int j = 0; j < TN; ++j) acc[i][j] += a[i] * b[j];
        }
        __syncthreads();
    }

    int crow0 = q0 + ty * TM;
    int ccol0 = c0 + tx * TN;
#pragma unroll
    for (int i = 0; i < TM; ++i)
#pragma unroll
        for (int j = 0; j < TN; ++j)
            C[(size_t)(crow0 + i) * T_SEQ + ccol0 + j] = acc[i][j] * scale;
}

// ---------------------------------------------------------------------------
// Causal softmax over rows; writes zeros beyond the diagonal.
// grid = N_HEADS * T_SEQ blocks, 256 threads each. blockIdx.x = h*T + row.
// ---------------------------------------------------------------------------
__inline__ __device__ float warp_max(float v) {
#pragma unroll
    for (int o = 16; o; o >>= 1) v = fmaxf(v, __shfl_xor_sync(0xffffffffu, v, o));
    return v;
}
__inline__ __device__ float warp_sum(float v) {
#pragma unroll
    for (int o = 16; o; o >>= 1) v += __shfl_xor_sync(0xffffffffu, v, o);
    return v;
}

__global__ __launch_bounds__(256)
void softmax_causal(float* __restrict__ sc)
{
    const int row = blockIdx.x & (T_SEQ - 1);
    float* p = sc + (size_t)blockIdx.x * T_SEQ;
    const int len = row + 1;
    const int tid = threadIdx.x;
    const int lane = tid & 31;
    const int wid = tid >> 5;
    __shared__ float red[8];

    // max
    float m = -3.4e38f;
    for (int j = tid; j < len; j += 256) m = fmaxf(m, p[j]);
    m = warp_max(m);
    if (lane == 0) red[wid] = m;
    __syncthreads();
    if (wid == 0) {
        float x = (lane < 8) ? red[lane] : -3.4e38f;
        x = warp_max(x);
        if (lane == 0) red[0] = x;
    }
    __syncthreads();
    m = red[0];
    __syncthreads();

    // exp + sum
    float s = 0.f;
    for (int j = tid; j < len; j += 256) {
        float e = __expf(p[j] - m);
        p[j] = e;
        s += e;
    }
    s = warp_sum(s);
    if (lane == 0) red[wid] = s;
    __syncthreads();
    if (wid == 0) {
        float x = (lane < 8) ? red[lane] : 0.f;
        x = warp_sum(x);
        if (lane == 0) red[0] = x;
    }
    __syncthreads();
    const float inv = 1.f / red[0];

    for (int j = tid; j < len; j += 256) p[j] *= inv;
    for (int j = len + tid; j < T_SEQ; j += 256) p[j] = 0.f;
}

// ---------------------------------------------------------------------------
// Batched AV: Y[h][q][d] = sum_k A[h][q][k] * V[h/4][k][d]
// A is K-contiguous, V is N-contiguous (normal GEMM). K-loop bounded causally.
// grid = (1, T/BM, N_HEADS)
// ---------------------------------------------------------------------------
__global__ __launch_bounds__(NTHREADS)
void gemm_av(const float* __restrict__ Attn, const float* __restrict__ V,
             float* __restrict__ Y)
{
    const int h = blockIdx.z;
    const int q0 = blockIdx.y * BM;
    const float* A = Attn + (size_t)h * T_SEQ * T_SEQ + (size_t)q0 * T_SEQ;
    const float* B = V + (size_t)(h >> 2) * HEAD_DIM;     // ldb = KV_DIM
    float* C = Y + (size_t)h * HEAD_DIM;                  // ldc = D_MODEL

    const int kmax = q0 + BM;   // causal upper bound (multiple of BK)

    __shared__ __align__(16) float As[BK][BM];
    __shared__ __align__(16) float Bs[BK][BN];

    const int tid = threadIdx.x;
    const int tx = tid % 16;
    const int ty = tid / 16;

    float acc[TM][TN];
#pragma unroll
    for (int i = 0; i < TM; ++i)
#pragma unroll
        for (int j = 0; j < TN; ++j) acc[i][j] = 0.f;

    for (int k0 = 0; k0 < kmax; k0 += BK) {
#pragma unroll
        for (int it = 0; it < 2; ++it) {
            int idx = tid + it * NTHREADS;
            // A tile: BM x BK, K-contiguous
            int arow = idx >> 2;
            int ac4  = idx & 3;
            float4 va = *(const float4*)(A + (size_t)arow * T_SEQ + k0 + ac4 * 4);
            As[ac4 * 4 + 0][arow] = va.x;
            As[ac4 * 4 + 1][arow] = va.y;
            As[ac4 * 4 + 2][arow] = va.z;
            As[ac4 * 4 + 3][arow] = va.w;
            // B tile: BK x BN, N-contiguous
            int brow = idx >> 5;        // 0..15
            int bc4  = idx & 31;        // 0..31
            float4 vb = *(const float4*)(B + (size_t)(k0 + brow) * KV_DIM + bc4 * 4);
            *(float4*)&Bs[brow][bc4 * 4] = vb;
        }
        __syncthreads();
#pragma unroll
        for (int k = 0; k < BK; ++k) {
            float4 a0 = *(const float4*)&As[k][ty * TM];
            float4 a1 = *(const float4*)&As[k][ty * TM + 4];
            float4 b0 = *(const float4*)&Bs[k][tx * TN];
            float4 b1 = *(const float4*)&Bs[k][tx * TN + 4];
            float a[TM] = {a0.x, a0.y, a0.z, a0.w, a1.x, a1.y, a1.z, a1.w};
            float b[TN] = {b0.x, b0.y, b0.z, b0.w, b1.x, b1.y, b1.z, b1.w};
#pragma unroll
            for (int i = 0; i < TM; ++i)
#pragma unroll
                for (int j = 0; j < TN; ++j) acc[i][j] += a[i] * b[j];
        }
        __syncthreads();
    }

    int crow0 = q0 + ty * TM;
    int ccol0 = tx * TN;
#pragma unroll
    for (int i = 0; i < TM; ++i)
#pragma unroll
        for (int j = 0; j < TN; ++j)
            C[(size_t)(crow0 + i) * D_MODEL + ccol0 + j] = acc[i][j];
}

// ---------------------------------------------------------------------------
// RoPE over q (32 heads) and k (8 heads), interleaved pairs.
// ---------------------------------------------------------------------------
__global__ __launch_bounds__(256)
void rope_kernel(float* __restrict__ q, float* __restrict__ k,
                 const float* __restrict__ cosp, const float* __restrict__ sinp)
{
    const int idx = blockIdx.x * blockDim.x + threadIdx.x;
    const int qpairs = T_SEQ * (D_MODEL / 2);     // 2048 * 2048
    const int kpairs = T_SEQ * (KV_DIM / 2);      // 2048 * 512
    if (idx < qpairs) {
        int t = idx / (D_MODEL / 2);
        int p = idx % (D_MODEL / 2);
        int i = p & 63;
        float c = cosp[t * 64 + i];
        float s = sinp[t * 64 + i];
        float* ptr = q + (size_t)t * D_MODEL + p * 2;
        float x1 = ptr[0], x2 = ptr[1];
        ptr[0] = x1 * c - x2 * s;
        ptr[1] = x1 * s + x2 * c;
    } else if (idx < qpairs + kpairs) {
        int r = idx - qpairs;
        int t = r / (KV_DIM / 2);
        int p = r % (KV_DIM / 2);
        int i = p & 63;
        float c = cosp[t * 64 + i];
        float s = sinp[t * 64 + i];
        float* ptr = k + (size_t)t * KV_DIM + p * 2;
        float x1 = ptr[0], x2 = ptr[1];
        ptr[0] = x1 * c - x2 * s;
        ptr[1] = x1 * s + x2 * c;
    }
}

// ---------------------------------------------------------------------------
// Launch
// ---------------------------------------------------------------------------
extern "C" void kernel_launch(void* const* d_in, const int* in_sizes, int n_in,
                              void* d_out, int out_size)
{
    const float* x    = (const float*)d_in[0];
    const float* cosp = (const float*)d_in[1];
    const float* sinp = (const float*)d_in[2];
    const float* wq   = (const float*)d_in[3];
    const float* wk   = (const float*)d_in[4];
    const float* wv   = (const float*)d_in[5];
    const float* wo   = (const float*)d_in[6];
    float* out = (float*)d_out;

    float *q, *k, *v, *y, *sc;
    cudaGetSymbolAddress((void**)&q,  g_q);
    cudaGetSymbolAddress((void**)&k,  g_k);
    cudaGetSymbolAddress((void**)&v,  g_v);
    cudaGetSymbolAddress((void**)&y,  g_y);
    cudaGetSymbolAddress((void**)&sc, g_scores);

    dim3 blk(NTHREADS);

    // Projections: C = A @ W^T
    gemm_nt<<<dim3(D_MODEL / BN, T_SEQ / BM), blk>>>(x, wq, q, D_MODEL, D_MODEL, D_MODEL, D_MODEL);
    gemm_nt<<<dim3(KV_DIM / BN, T_SEQ / BM), blk>>>(x, wk, k, D_MODEL, D_MODEL, D_MODEL, KV_DIM);
    gemm_nt<<<dim3(KV_DIM / BN, T_SEQ / BM), blk>>>(x, wv, v, D_MODEL, D_MODEL, D_MODEL, KV_DIM);

    // RoPE on q and k
    {
        int total = T_SEQ * (D_MODEL / 2) + T_SEQ * (KV_DIM / 2);
        rope_kernel<<<(total + 255) / 256, 256>>>(q, k, cosp, sinp);
    }

    // Scores (causal block skip) + softmax
    const float scale = 0.08838834764831845f;   // 1/sqrt(128)
    gemm_scores<<<dim3(T_SEQ / BN, T_SEQ / BM, N_HEADS), blk>>>(q, k, sc, scale);
    softmax_causal<<<N_HEADS * T_SEQ, 256>>>(sc);

    // AV (causally bounded K-loop)
    gemm_av<<<dim3(1, T_SEQ / BM, N_HEADS), blk>>>(sc, v, y);

    // Output projection
    gemm_nt<<<dim3(D_MODEL / BN, T_SEQ / BM), blk>>>(y, wo, out, D_MODEL, D_MODEL, D_MODEL, D_MODEL);
}

// round 2
// speedup vs baseline: 2.2508x; 2.2508x over previous
#include <cuda_runtime.h>
#include <stdint.h>
#include <math.h>

// ---------------------------------------------------------------------------
// Problem constants (B=1)
// ---------------------------------------------------------------------------
#define T_SEQ 2048
#define D_MODEL 4096
#define KV_DIM 1024
#define HEAD_DIM 128
#define N_HEADS 32
#define N_KV_HEADS 8

// GEMM tiling (tf32 tensor-core path)
#define BM 128
#define BN 128
#define BK 32
#define BKP 36            // padded k-stride in smem (floats)
#define NTHREADS 256

// ---------------------------------------------------------------------------
// Scratch (static device globals; no runtime allocation)
// ---------------------------------------------------------------------------
__device__ float g_q[T_SEQ * D_MODEL];                 // 32 MB
__device__ float g_k[T_SEQ * KV_DIM];                  // 8 MB
__device__ float g_v[T_SEQ * KV_DIM];                  // 8 MB
__device__ float g_y[T_SEQ * D_MODEL];                 // 32 MB
__device__ float g_scores[134217728];                  // 32*2048*2048 = 512 MB

// ---------------------------------------------------------------------------
// tf32 helpers
// ---------------------------------------------------------------------------
__device__ __forceinline__ uint32_t f2tf(float f) {
    uint32_t u;
    asm("cvt.rna.tf32.f32 %0, %1;" : "=r"(u) : "f"(f));
    return u;
}

// k-column permutation within each 8-group so that (k, k+4) pairs are adjacent
// and fragment loads become single 64-bit LDS:
//   col(k) = (k & ~7) + 2*(k & 3) + ((k >> 2) & 1)
// Staging writes apply the permutation; fragment loads read uint2 at kk + 2t.

// ---------------------------------------------------------------------------
// Core mma tile: 8 warps, warp_m in [0,4), warp_n in [0,2).
// Each warp: 32(M) x 64(N). acc[2][8][4].
// ---------------------------------------------------------------------------
__device__ __forceinline__ void mma_bk(const uint32_t (*As)[BKP], const uint32_t (*Bs)[BKP],
                                       int warp_m, int warp_n, int lane,
                                       float acc[2][8][4])
{
    const int g = lane >> 2;
    const int t = lane & 3;
#pragma unroll
    for (int kk = 0; kk < BK; kk += 8) {
        uint32_t a[2][4];
#pragma unroll
        for (int i = 0; i < 2; ++i) {
            int r0 = warp_m * 32 + i * 16 + g;
            uint2 lo = *(const uint2*)&As[r0][kk + 2 * t];      // (k=t, k=t+4)
            uint2 hi = *(const uint2*)&As[r0 + 8][kk + 2 * t];
            a[i][0] = lo.x; a[i][1] = hi.x; a[i][2] = lo.y; a[i][3] = hi.y;
        }
#pragma unroll
        for (int j = 0; j < 8; ++j) {
            int n0 = warp_n * 64 + j * 8 + g;
            uint2 bb = *(const uint2*)&Bs[n0][kk + 2 * t];       // (k=t, k=t+4)
#pragma unroll
            for (int i = 0; i < 2; ++i) {
                asm volatile(
                    "mma.sync.aligned.m16n8k8.row.col.f32.tf32.tf32.f32 "
                    "{%0,%1,%2,%3}, {%4,%5,%6,%7}, {%8,%9}, {%0,%1,%2,%3};\n"
                    : "+f"(acc[i][j][0]), "+f"(acc[i][j][1]),
                      "+f"(acc[i][j][2]), "+f"(acc[i][j][3])
                    : "r"(a[i][0]), "r"(a[i][1]), "r"(a[i][2]), "r"(a[i][3]),
                      "r"(bb.x), "r"(bb.y));
            }
        }
    }
}

// Stage a BM x BK tile (K-contiguous source) with tf32 convert + k-permute.
__device__ __forceinline__ void stage_kcontig(const float* __restrict__ src, int ld,
                                              int k0, uint32_t (*dst)[BKP], int tid)
{
#pragma unroll
    for (int it = 0; it < 4; ++it) {
        int idx = tid + it * NTHREADS;     // 0..1023
        int row = idx >> 3;                // 0..127
        int kl  = (idx & 7) * 4;           // 0,4,...,28
        int base = kl & ~7;
        int bit  = (kl >> 2) & 1;
        float4 v = *(const float4*)(src + (size_t)row * ld + k0 + kl);
        dst[row][base + bit + 0] = f2tf(v.x);
        dst[row][base + bit + 2] = f2tf(v.y);
        dst[row][base + bit + 4] = f2tf(v.z);
        dst[row][base + bit + 6] = f2tf(v.w);
    }
}

// Stage a BK x BN tile (N-contiguous source) transposed into [N][K] + permute.
__device__ __forceinline__ void stage_ncontig_T(const float* __restrict__ src, int ld,
                                                int k0, uint32_t (*dst)[BKP], int tid)
{
#pragma unroll
    for (int it = 0; it < 4; ++it) {
        int idx = tid + it * NTHREADS;     // 0..1023
        int krow = idx >> 5;               // 0..31
        int nc   = (idx & 31) * 4;         // 0..124
        int col = (krow & ~7) + 2 * (krow & 3) + ((krow >> 2) & 1);
        float4 v = *(const float4*)(src + (size_t)(k0 + krow) * ld + nc);
        dst[nc + 0][col] = f2tf(v.x);
        dst[nc + 1][col] = f2tf(v.y);
        dst[nc + 2][col] = f2tf(v.z);
        dst[nc + 3][col] = f2tf(v.w);
    }
}

__device__ __forceinline__ void store_acc(float* __restrict__ C, int ldc,
                                          int row_base, int col_base,
                                          int warp_m, int warp_n, int lane,
                                          float acc[2][8][4], float scale)
{
    const int g = lane >> 2;
    const int t = lane & 3;
#pragma unroll
    for (int i = 0; i < 2; ++i) {
#pragma unroll
        for (int j = 0; j < 8; ++j) {
            int r = row_base + warp_m * 32 + i * 16 + g;
            int c = col_base + warp_n * 64 + j * 8 + t * 2;
            float2 v0 = make_float2(acc[i][j][0] * scale, acc[i][j][1] * scale);
            float2 v1 = make_float2(acc[i][j][2] * scale, acc[i][j][3] * scale);
            *(float2*)(C + (size_t)r * ldc + c) = v0;
            *(float2*)(C + (size_t)(r + 8) * ldc + c) = v1;
        }
    }
}

// ---------------------------------------------------------------------------
// GEMM NT: C[M,N] = A[M,K] * B[N,K]^T  (both K-contiguous)
// grid = (N/BN, M/BM)
// ---------------------------------------------------------------------------
__global__ __launch_bounds__(NTHREADS)
void gemm_tf32_nt(const float* __restrict__ A, const float* __restrict__ B,
                  float* __restrict__ C, int K, int lda, int ldb, int ldc)
{
    __shared__ uint32_t As[BM][BKP];
    __shared__ uint32_t Bs[BN][BKP];

    const int tid = threadIdx.x;
    const int lane = tid & 31;
    const int wid = tid >> 5;
    const int warp_m = wid & 3;
    const int warp_n = wid >> 2;

    const float* Ab = A + (size_t)blockIdx.y * BM * lda;
    const float* Bb = B + (size_t)blockIdx.x * BN * ldb;

    float acc[2][8][4];
#pragma unroll
    for (int i = 0; i < 2; ++i)
#pragma unroll
        for (int j = 0; j < 8; ++j)
#pragma unroll
            for (int r = 0; r < 4; ++r) acc[i][j][r] = 0.f;

    for (int k0 = 0; k0 < K; k0 += BK) {
        stage_kcontig(Ab, lda, k0, As, tid);
        stage_kcontig(Bb, ldb, k0, Bs, tid);
        __syncthreads();
        mma_bk(As, Bs, warp_m, warp_n, lane, acc);
        __syncthreads();
    }

    store_acc(C, ldc, blockIdx.y * BM, blockIdx.x * BN, warp_m, warp_n, lane, acc, 1.0f);
}

// ---------------------------------------------------------------------------
// Scores: S[h][q][k] = scale * Q[h] . K[h/4], causal block skip
// grid = (T/BN, T/BM, N_HEADS)
// ---------------------------------------------------------------------------
__global__ __launch_bounds__(NTHREADS)
void gemm_scores_tf32(const float* __restrict__ Q, const float* __restrict__ Kt,
                      float* __restrict__ S, float scale)
{
    const int h = blockIdx.z;
    const int q0 = blockIdx.y * BM;
    const int c0 = blockIdx.x * BN;
    if (c0 > q0 + BM - 1) return;   // fully above causal diagonal

    __shared__ uint32_t As[BM][BKP];
    __shared__ uint32_t Bs[BN][BKP];

    const int tid = threadIdx.x;
    const int lane = tid & 31;
    const int wid = tid >> 5;
    const int warp_m = wid & 3;
    const int warp_n = wid >> 2;

    const float* Ab = Q + (size_t)q0 * D_MODEL + (size_t)h * HEAD_DIM;
    const float* Bb = Kt + (size_t)c0 * KV_DIM + (size_t)(h >> 2) * HEAD_DIM;
    float* C = S + (size_t)h * T_SEQ * T_SEQ;

    float acc[2][8][4];
#pragma unroll
    for (int i = 0; i < 2; ++i)
#pragma unroll
        for (int j = 0; j < 8; ++j)
#pragma unroll
            for (int r = 0; r < 4; ++r) acc[i][j][r] = 0.f;

#pragma unroll
    for (int k0 = 0; k0 < HEAD_DIM; k0 += BK) {
        stage_kcontig(Ab, D_MODEL, k0, As, tid);
        stage_kcontig(Bb, KV_DIM, k0, Bs, tid);
        __syncthreads();
        mma_bk(As, Bs, warp_m, warp_n, lane, acc);
        __syncthreads();
    }

    store_acc(C, T_SEQ, q0, c0, warp_m, warp_n, lane, acc, scale);
}

// ---------------------------------------------------------------------------
// AV: Y[h][q][d] = sum_k Attn[h][q][k] * V[h/4][k][d], causal K bound
// grid = (1, T/BM, N_HEADS)
// ---------------------------------------------------------------------------
__global__ __launch_bounds__(NTHREADS)
void gemm_av_tf32(const float* __restrict__ Attn, const float* __restrict__ V,
                  float* __restrict__ Y)
{
    const int h = blockIdx.z;
    const int q0 = blockIdx.y * BM;

    __shared__ uint32_t As[BM][BKP];
    __shared__ uint32_t Bs[BN][BKP];

    const int tid = threadIdx.x;
    const int lane = tid & 31;
    const int wid = tid >> 5;
    const int warp_m = wid & 3;
    const int warp_n = wid >> 2;

    const float* Ab = Attn + (size_t)h * T_SEQ * T_SEQ + (size_t)q0 * T_SEQ;
    const float* Bb = V + (size_t)(h >> 2) * HEAD_DIM;     // ld = KV_DIM, N-contiguous
    float* C = Y + (size_t)h * HEAD_DIM;                   // ldc = D_MODEL

    const int kmax = q0 + BM;

    float acc[2][8][4];
#pragma unroll
    for (int i = 0; i < 2; ++i)
#pragma unroll
        for (int j = 0; j < 8; ++j)
#pragma unroll
            for (int r = 0; r < 4; ++r) acc[i][j][r] = 0.f;

    for (int k0 = 0; k0 < kmax; k0 += BK) {
        stage_kcontig(Ab, T_SEQ, k0, As, tid);
        stage_ncontig_T(Bb, KV_DIM, k0, Bs, tid);
        __syncthreads();
        mma_bk(As, Bs, warp_m, warp_n, lane, acc);
        __syncthreads();
    }

    store_acc(C, D_MODEL, q0, 0, warp_m, warp_n, lane, acc, 1.0f);
}

// ---------------------------------------------------------------------------
// Causal softmax over rows; zeros beyond the diagonal.
// ---------------------------------------------------------------------------
__inline__ __device__ float warp_max(float v) {
#pragma unroll
    for (int o = 16; o; o >>= 1) v = fmaxf(v, __shfl_xor_sync(0xffffffffu, v, o));
    return v;
}
__inline__ __device__ float warp_sum(float v) {
#pragma unroll
    for (int o = 16; o; o >>= 1) v += __shfl_xor_sync(0xffffffffu, v, o);
    return v;
}

__global__ __launch_bounds__(256)
void softmax_causal(float* __restrict__ sc)
{
    const int row = blockIdx.x & (T_SEQ - 1);
    float* p = sc + (size_t)blockIdx.x * T_SEQ;
    const int len = row + 1;
    const int tid = threadIdx.x;
    const int lane = tid & 31;
    const int wid = tid >> 5;
    __shared__ float red[8];

    float m = -3.4e38f;
    for (int j = tid; j < len; j += 256) m = fmaxf(m, p[j]);
    m = warp_max(m);
    if (lane == 0) red[wid] = m;
    __syncthreads();
    if (wid == 0) {
        float x = (lane < 8) ? red[lane] : -3.4e38f;
        x = warp_max(x);
        if (lane == 0) red[0] = x;
    }
    __syncthreads();
    m = red[0];
    __syncthreads();

    float s = 0.f;
    for (int j = tid; j < len; j += 256) {
        float e = __expf(p[j] - m);
        p[j] = e;
        s += e;
    }
    s = warp_sum(s);
    if (lane == 0) red[wid] = s;
    __syncthreads();
    if (wid == 0) {
        float x = (lane < 8) ? red[lane] : 0.f;
        x = warp_sum(x);
        if (lane == 0) red[0] = x;
    }
    __syncthreads();
    const float inv = 1.f / red[0];

    for (int j = tid; j < len; j += 256) p[j] *= inv;
    for (int j = len + tid; j < T_SEQ; j += 256) p[j] = 0.f;
}

// ---------------------------------------------------------------------------
// RoPE over q (32 heads) and k (8 heads), interleaved pairs.
// ---------------------------------------------------------------------------
__global__ __launch_bounds__(256)
void rope_kernel(float* __restrict__ q, float* __restrict__ k,
                 const float* __restrict__ cosp, const float* __restrict__ sinp)
{
    const int idx = blockIdx.x * blockDim.x + threadIdx.x;
    const int qpairs = T_SEQ * (D_MODEL / 2);
    const int kpairs = T_SEQ * (KV_DIM / 2);
    if (idx < qpairs) {
        int t = idx / (D_MODEL / 2);
        int p = idx % (D_MODEL / 2);
        int i = p & 63;
        float c = cosp[t * 64 + i];
        float s = sinp[t * 64 + i];
        float* ptr = q + (size_t)t * D_MODEL + p * 2;
        float x1 = ptr[0], x2 = ptr[1];
        ptr[0] = x1 * c - x2 * s;
        ptr[1] = x1 * s + x2 * c;
    } else if (idx < qpairs + kpairs) {
        int r = idx - qpairs;
        int t = r / (KV_DIM / 2);
        int p = r % (KV_DIM / 2);
        int i = p & 63;
        float c = cosp[t * 64 + i];
        float s = sinp[t * 64 + i];
        float* ptr = k + (size_t)t * KV_DIM + p * 2;
        float x1 = ptr[0], x2 = ptr[1];
        ptr[0] = x1 * c - x2 * s;
        ptr[1] = x1 * s + x2 * c;
    }
}

// ---------------------------------------------------------------------------
// Launch
// ---------------------------------------------------------------------------
extern "C" void kernel_launch(void* const* d_in, const int* in_sizes, int n_in,
                              void* d_out, int out_size)
{
    const float* x    = (const float*)d_in[0];
    const float* cosp = (const float*)d_in[1];
    const float* sinp = (const float*)d_in[2];
    const float* wq   = (const float*)d_in[3];
    const float* wk   = (const float*)d_in[4];
    const float* wv   = (const float*)d_in[5];
    const float* wo   = (const float*)d_in[6];
    float* out = (float*)d_out;

    float *q, *k, *v, *y, *sc;
    cudaGetSymbolAddress((void**)&q,  g_q);
    cudaGetSymbolAddress((void**)&k,  g_k);
    cudaGetSymbolAddress((void**)&v,  g_v);
    cudaGetSymbolAddress((void**)&y,  g_y);
    cudaGetSymbolAddress((void**)&sc, g_scores);

    dim3 blk(NTHREADS);

    gemm_tf32_nt<<<dim3(D_MODEL / BN, T_SEQ / BM), blk>>>(x, wq, q, D_MODEL, D_MODEL, D_MODEL, D_MODEL);
    gemm_tf32_nt<<<dim3(KV_DIM / BN, T_SEQ / BM), blk>>>(x, wk, k, D_MODEL, D_MODEL, D_MODEL, KV_DIM);
    gemm_tf32_nt<<<dim3(KV_DIM / BN, T_SEQ / BM), blk>>>(x, wv, v, D_MODEL, D_MODEL, D_MODEL, KV_DIM);

    {
        int total = T_SEQ * (D_MODEL / 2) + T_SEQ * (KV_DIM / 2);
        rope_kernel<<<(total + 255) / 256, 256>>>(q, k, cosp, sinp);
    }

    const float scale = 0.08838834764831845f;   // 1/sqrt(128)
    gemm_scores_tf32<<<dim3(T_SEQ / BN, T_SEQ / BM, N_HEADS), blk>>>(q, k, sc, scale);
    softmax_causal<<<N_HEADS * T_SEQ, 256>>>(sc);
    gemm_av_tf32<<<dim3(1, T_SEQ / BM, N_HEADS), blk>>>(sc, v, y);

    gemm_tf32_nt<<<dim3(D_MODEL / BN, T_SEQ / BM), blk>>>(y, wo, out, D_MODEL, D_MODEL, D_MODEL, D_MODEL);
}

// round 3
// speedup vs baseline: 2.2933x; 1.0189x over previous
#include <cuda_runtime.h>
#include <stdint.h>
#include <math.h>

// ---------------------------------------------------------------------------
// Problem constants (B=1)
// ---------------------------------------------------------------------------
#define T_SEQ 2048
#define D_MODEL 4096
#define KV_DIM 1024
#define HEAD_DIM 128
#define N_HEADS 32
#define N_KV_HEADS 8

// GEMM tiling (tf32 tensor-core path)
#define BM 128
#define BN 128
#define BK 32
#define BKP 36            // padded k-stride in smem (floats)
#define NTHREADS 256

// ---------------------------------------------------------------------------
// Scratch (static device globals; no runtime allocation)
// ---------------------------------------------------------------------------
__device__ float g_q[T_SEQ * D_MODEL];                 // 32 MB
__device__ float g_k[T_SEQ * KV_DIM];                  // 8 MB
__device__ float g_v[T_SEQ * KV_DIM];                  // 8 MB
__device__ float g_y[T_SEQ * D_MODEL];                 // 32 MB
__device__ float g_scores[134217728];                  // 32*2048*2048 = 512 MB

// ---------------------------------------------------------------------------
// tf32 helpers
// ---------------------------------------------------------------------------
__device__ __forceinline__ uint32_t f2tf(float f) {
    uint32_t u;
    asm("cvt.rna.tf32.f32 %0, %1;" : "=r"(u) : "f"(f));
    return u;
}

// k-column permutation within each 8-group so that (k, k+4) pairs are adjacent
// and fragment loads become single 64-bit LDS:
//   col(k) = (k & ~7) + 2*(k & 3) + ((k >> 2) & 1)

// ---------------------------------------------------------------------------
// Core mma tile: 8 warps, warp_m in [0,4), warp_n in [0,2).
// Each warp: 32(M) x 64(N). acc[2][8][4].
// ---------------------------------------------------------------------------
__device__ __forceinline__ void mma_bk(const uint32_t (*As)[BKP], const uint32_t (*Bs)[BKP],
                                       int warp_m, int warp_n, int lane,
                                       float acc[2][8][4])
{
    const int g = lane >> 2;
    const int t = lane & 3;
#pragma unroll
    for (int kk = 0; kk < BK; kk += 8) {
        uint32_t a[2][4];
#pragma unroll
        for (int i = 0; i < 2; ++i) {
            int r0 = warp_m * 32 + i * 16 + g;
            uint2 lo = *(const uint2*)&As[r0][kk + 2 * t];      // (k=t, k=t+4)
            uint2 hi = *(const uint2*)&As[r0 + 8][kk + 2 * t];
            a[i][0] = lo.x; a[i][1] = hi.x; a[i][2] = lo.y; a[i][3] = hi.y;
        }
#pragma unroll
        for (int j = 0; j < 8; ++j) {
            int n0 = warp_n * 64 + j * 8 + g;
            uint2 bb = *(const uint2*)&Bs[n0][kk + 2 * t];       // (k=t, k=t+4)
#pragma unroll
            for (int i = 0; i < 2; ++i) {
                asm volatile(
                    "mma.sync.aligned.m16n8k8.row.col.f32.tf32.tf32.f32 "
                    "{%0,%1,%2,%3}, {%4,%5,%6,%7}, {%8,%9}, {%0,%1,%2,%3};\n"
                    : "+f"(acc[i][j][0]), "+f"(acc[i][j][1]),
                      "+f"(acc[i][j][2]), "+f"(acc[i][j][3])
                    : "r"(a[i][0]), "r"(a[i][1]), "r"(a[i][2]), "r"(a[i][3]),
                      "r"(bb.x), "r"(bb.y));
            }
        }
    }
}

// ---------------------------------------------------------------------------
// Tile fetch (global -> regs) and store (regs -> smem with cvt + permute)
// ---------------------------------------------------------------------------
// K-contiguous BM x BK tile
__device__ __forceinline__ void fetch_kcontig(const float* __restrict__ src, int ld,
                                              int k0, float4* r, int tid)
{
#pragma unroll
    for (int it = 0; it < 4; ++it) {
        int idx = tid + it * NTHREADS;     // 0..1023
        int row = idx >> 3;                // 0..127
        int kl  = (idx & 7) * 4;           // 0..28
        r[it] = *(const float4*)(src + (size_t)row * ld + k0 + kl);
    }
}

__device__ __forceinline__ void store_kcontig(const float4* r, uint32_t (*dst)[BKP], int tid)
{
#pragma unroll
    for (int it = 0; it < 4; ++it) {
        int idx = tid + it * NTHREADS;
        int row = idx >> 3;
        int kl  = (idx & 7) * 4;
        int base = kl & ~7;
        int bit  = (kl >> 2) & 1;
        dst[row][base + bit + 0] = f2tf(r[it].x);
        dst[row][base + bit + 2] = f2tf(r[it].y);
        dst[row][base + bit + 4] = f2tf(r[it].z);
        dst[row][base + bit + 6] = f2tf(r[it].w);
    }
}

// N-contiguous BK x BN tile, stored transposed [N][K]
__device__ __forceinline__ void fetch_ncontig(const float* __restrict__ src, int ld,
                                              int k0, float4* r, int tid)
{
#pragma unroll
    for (int it = 0; it < 4; ++it) {
        int idx = tid + it * NTHREADS;
        int krow = idx >> 5;               // 0..31
        int nc   = (idx & 31) * 4;         // 0..124
        r[it] = *(const float4*)(src + (size_t)(k0 + krow) * ld + nc);
    }
}

__device__ __forceinline__ void store_ncontig_T(const float4* r, uint32_t (*dst)[BKP], int tid)
{
#pragma unroll
    for (int it = 0; it < 4; ++it) {
        int idx = tid + it * NTHREADS;
        int krow = idx >> 5;
        int nc   = (idx & 31) * 4;
        int col = (krow & ~7) + 2 * (krow & 3) + ((krow >> 2) & 1);
        dst[nc + 0][col] = f2tf(r[it].x);
        dst[nc + 1][col] = f2tf(r[it].y);
        dst[nc + 2][col] = f2tf(r[it].z);
        dst[nc + 3][col] = f2tf(r[it].w);
    }
}

__device__ __forceinline__ void store_acc(float* __restrict__ C, int ldc,
                                          int row_base, int col_base,
                                          int warp_m, int warp_n, int lane,
                                          float acc[2][8][4], float scale)
{
    const int g = lane >> 2;
    const int t = lane & 3;
#pragma unroll
    for (int i = 0; i < 2; ++i) {
#pragma unroll
        for (int j = 0; j < 8; ++j) {
            int r = row_base + warp_m * 32 + i * 16 + g;
            int c = col_base + warp_n * 64 + j * 8 + t * 2;
            float2 v0 = make_float2(acc[i][j][0] * scale, acc[i][j][1] * scale);
            float2 v1 = make_float2(acc[i][j][2] * scale, acc[i][j][3] * scale);
            *(float2*)(C + (size_t)r * ldc + c) = v0;
            *(float2*)(C + (size_t)(r + 8) * ldc + c) = v1;
        }
    }
}

// ---------------------------------------------------------------------------
// GEMM NT: C[M,N] = A[M,K] * B[N,K]^T  (both K-contiguous), prefetched
// grid = (N/BN, M/BM)
// ---------------------------------------------------------------------------
__global__ __launch_bounds__(NTHREADS)
void gemm_tf32_nt(const float* __restrict__ A, const float* __restrict__ B,
                  float* __restrict__ C, int K, int lda, int ldb, int ldc)
{
    __shared__ uint32_t As[BM][BKP];
    __shared__ uint32_t Bs[BN][BKP];

    const int tid = threadIdx.x;
    const int lane = tid & 31;
    const int wid = tid >> 5;
    const int warp_m = wid & 3;
    const int warp_n = wid >> 2;

    const float* Ab = A + (size_t)blockIdx.y * BM * lda;
    const float* Bb = B + (size_t)blockIdx.x * BN * ldb;

    float acc[2][8][4];
#pragma unroll
    for (int i = 0; i < 2; ++i)
#pragma unroll
        for (int j = 0; j < 8; ++j)
#pragma unroll
            for (int r = 0; r < 4; ++r) acc[i][j][r] = 0.f;

    float4 ra[4], rb[4];
    fetch_kcontig(Ab, lda, 0, ra, tid);
    fetch_kcontig(Bb, ldb, 0, rb, tid);

    for (int k0 = 0; k0 < K; k0 += BK) {
        store_kcontig(ra, As, tid);
        store_kcontig(rb, Bs, tid);
        __syncthreads();
        if (k0 + BK < K) {
            fetch_kcontig(Ab, lda, k0 + BK, ra, tid);
            fetch_kcontig(Bb, ldb, k0 + BK, rb, tid);
        }
        mma_bk(As, Bs, warp_m, warp_n, lane, acc);
        __syncthreads();
    }

    store_acc(C, ldc, blockIdx.y * BM, blockIdx.x * BN, warp_m, warp_n, lane, acc, 1.0f);
}

// ---------------------------------------------------------------------------
// Scores: S[h][q][k] = scale * Q[h] . K[h/4], causal block skip, prefetched
// grid = (T/BN, T/BM, N_HEADS)
// ---------------------------------------------------------------------------
__global__ __launch_bounds__(NTHREADS)
void gemm_scores_tf32(const float* __restrict__ Q, const float* __restrict__ Kt,
                      float* __restrict__ S, float scale)
{
    const int h = blockIdx.z;
    const int q0 = blockIdx.y * BM;
    const int c0 = blockIdx.x * BN;
    if (c0 > q0 + BM - 1) return;   // fully above causal diagonal

    __shared__ uint32_t As[BM][BKP];
    __shared__ uint32_t Bs[BN][BKP];

    const int tid = threadIdx.x;
    const int lane = tid & 31;
    const int wid = tid >> 5;
    const int warp_m = wid & 3;
    const int warp_n = wid >> 2;

    const float* Ab = Q + (size_t)q0 * D_MODEL + (size_t)h * HEAD_DIM;
    const float* Bb = Kt + (size_t)c0 * KV_DIM + (size_t)(h >> 2) * HEAD_DIM;
    float* C = S + (size_t)h * T_SEQ * T_SEQ;

    float acc[2][8][4];
#pragma unroll
    for (int i = 0; i < 2; ++i)
#pragma unroll
        for (int j = 0; j < 8; ++j)
#pragma unroll
            for (int r = 0; r < 4; ++r) acc[i][j][r] = 0.f;

    float4 ra[4], rb[4];
    fetch_kcontig(Ab, D_MODEL, 0, ra, tid);
    fetch_kcontig(Bb, KV_DIM, 0, rb, tid);

#pragma unroll
    for (int k0 = 0; k0 < HEAD_DIM; k0 += BK) {
        store_kcontig(ra, As, tid);
        store_kcontig(rb, Bs, tid);
        __syncthreads();
        if (k0 + BK < HEAD_DIM) {
            fetch_kcontig(Ab, D_MODEL, k0 + BK, ra, tid);
            fetch_kcontig(Bb, KV_DIM, k0 + BK, rb, tid);
        }
        mma_bk(As, Bs, warp_m, warp_n, lane, acc);
        __syncthreads();
    }

    store_acc(C, T_SEQ, q0, c0, warp_m, warp_n, lane, acc, scale);
}

// ---------------------------------------------------------------------------
// AV: Y[h][q][d] = sum_k Attn[h][q][k] * V[h/4][k][d], causal K bound, prefetched
// grid = (1, T/BM, N_HEADS)
// ---------------------------------------------------------------------------
__global__ __launch_bounds__(NTHREADS)
void gemm_av_tf32(const float* __restrict__ Attn, const float* __restrict__ V,
                  float* __restrict__ Y)
{
    const int h = blockIdx.z;
    const int q0 = blockIdx.y * BM;

    __shared__ uint32_t As[BM][BKP];
    __shared__ uint32_t Bs[BN][BKP];

    const int tid = threadIdx.x;
    const int lane = tid & 31;
    const int wid = tid >> 5;
    const int warp_m = wid & 3;
    const int warp_n = wid >> 2;

    const float* Ab = Attn + (size_t)h * T_SEQ * T_SEQ + (size_t)q0 * T_SEQ;
    const float* Bb = V + (size_t)(h >> 2) * HEAD_DIM;     // ld = KV_DIM, N-contiguous
    float* C = Y + (size_t)h * HEAD_DIM;                   // ldc = D_MODEL

    const int kmax = q0 + BM;

    float acc[2][8][4];
#pragma unroll
    for (int i = 0; i < 2; ++i)
#pragma unroll
        for (int j = 0; j < 8; ++j)
#pragma unroll
            for (int r = 0; r < 4; ++r) acc[i][j][r] = 0.f;

    float4 ra[4], rb[4];
    fetch_kcontig(Ab, T_SEQ, 0, ra, tid);
    fetch_ncontig(Bb, KV_DIM, 0, rb, tid);

    for (int k0 = 0; k0 < kmax; k0 += BK) {
        store_kcontig(ra, As, tid);
        store_ncontig_T(rb, Bs, tid);
        __syncthreads();
        if (k0 + BK < kmax) {
            fetch_kcontig(Ab, T_SEQ, k0 + BK, ra, tid);
            fetch_ncontig(Bb, KV_DIM, k0 + BK, rb, tid);
        }
        mma_bk(As, Bs, warp_m, warp_n, lane, acc);
        __syncthreads();
    }

    store_acc(C, D_MODEL, q0, 0, warp_m, warp_n, lane, acc, 1.0f);
}

// ---------------------------------------------------------------------------
// Causal softmax over rows; zeros only to the end of the 128-wide diag block
// (AV never reads columns >= (row|127)+1).
// ---------------------------------------------------------------------------
__inline__ __device__ float warp_max(float v) {
#pragma unroll
    for (int o = 16; o; o >>= 1) v = fmaxf(v, __shfl_xor_sync(0xffffffffu, v, o));
    return v;
}
__inline__ __device__ float warp_sum(float v) {
#pragma unroll
    for (int o = 16; o; o >>= 1) v += __shfl_xor_sync(0xffffffffu, v, o);
    return v;
}

__global__ __launch_bounds__(256)
void softmax_causal(float* __restrict__ sc)
{
    const int row = blockIdx.x & (T_SEQ - 1);
    float* p = sc + (size_t)blockIdx.x * T_SEQ;
    const int len = row + 1;
    const int fill_end = (row | (BM - 1)) + 1;   // end of this row's diagonal block
    const int tid = threadIdx.x;
    const int lane = tid & 31;
    const int wid = tid >> 5;
    __shared__ float red[8];

    float m = -3.4e38f;
    for (int j = tid; j < len; j += 256) m = fmaxf(m, p[j]);
    m = warp_max(m);
    if (lane == 0) red[wid] = m;
    __syncthreads();
    if (wid == 0) {
        float x = (lane < 8) ? red[lane] : -3.4e38f;
        x = warp_max(x);
        if (lane == 0) red[0] = x;
    }
    __syncthreads();
    m = red[0];
    __syncthreads();

    float s = 0.f;
    for (int j = tid; j < len; j += 256) {
        float e = __expf(p[j] - m);
        p[j] = e;
        s += e;
    }
    s = warp_sum(s);
    if (lane == 0) red[wid] = s;
    __syncthreads();
    if (wid == 0) {
        float x = (lane < 8) ? red[lane] : 0.f;
        x = warp_sum(x);
        if (lane == 0) red[0] = x;
    }
    __syncthreads();
    const float inv = 1.f / red[0];

    for (int j = tid; j < len; j += 256) p[j] *= inv;
    for (int j = len + tid; j < fill_end; j += 256) p[j] = 0.f;
}

// ---------------------------------------------------------------------------
// RoPE over q (32 heads) and k (8 heads), interleaved pairs.
// ---------------------------------------------------------------------------
__global__ __launch_bounds__(256)
void rope_kernel(float* __restrict__ q, float* __restrict__ k,
                 const float* __restrict__ cosp, const float* __restrict__ sinp)
{
    const int idx = blockIdx.x * blockDim.x + threadIdx.x;
    const int qpairs = T_SEQ * (D_MODEL / 2);
    const int kpairs = T_SEQ * (KV_DIM / 2);
    if (idx < qpairs) {
        int t = idx / (D_MODEL / 2);
        int p = idx % (D_MODEL / 2);
        int i = p & 63;
        float c = cosp[t * 64 + i];
        float s = sinp[t * 64 + i];
        float* ptr = q + (size_t)t * D_MODEL + p * 2;
        float x1 = ptr[0], x2 = ptr[1];
        ptr[0] = x1 * c - x2 * s;
        ptr[1] = x1 * s + x2 * c;
    } else if (idx < qpairs + kpairs) {
        int r = idx - qpairs;
        int t = r / (KV_DIM / 2);
        int p = r % (KV_DIM / 2);
        int i = p & 63;
        float c = cosp[t * 64 + i];
        float s = sinp[t * 64 + i];
        float* ptr = k + (size_t)t * KV_DIM + p * 2;
        float x1 = ptr[0], x2 = ptr[1];
        ptr[0] = x1 * c - x2 * s;
        ptr[1] = x1 * s + x2 * c;
    }
}

// ---------------------------------------------------------------------------
// Launch
// ---------------------------------------------------------------------------
extern "C" void kernel_launch(void* const* d_in, const int* in_sizes, int n_in,
                              void* d_out, int out_size)
{
    const float* x    = (const float*)d_in[0];
    const float* cosp = (const float*)d_in[1];
    const float* sinp = (const float*)d_in[2];
    const float* wq   = (const float*)d_in[3];
    const float* wk   = (const float*)d_in[4];
    const float* wv   = (const float*)d_in[5];
    const float* wo   = (const float*)d_in[6];
    float* out = (float*)d_out;

    float *q, *k, *v, *y, *sc;
    cudaGetSymbolAddress((void**)&q,  g_q);
    cudaGetSymbolAddress((void**)&k,  g_k);
    cudaGetSymbolAddress((void**)&v,  g_v);
    cudaGetSymbolAddress((void**)&y,  g_y);
    cudaGetSymbolAddress((void**)&sc, g_scores);

    dim3 blk(NTHREADS);

    gemm_tf32_nt<<<dim3(D_MODEL / BN, T_SEQ / BM), blk>>>(x, wq, q, D_MODEL, D_MODEL, D_MODEL, D_MODEL);
    gemm_tf32_nt<<<dim3(KV_DIM / BN, T_SEQ / BM), blk>>>(x, wk, k, D_MODEL, D_MODEL, D_MODEL, KV_DIM);
    gemm_tf32_nt<<<dim3(KV_DIM / BN, T_SEQ / BM), blk>>>(x, wv, v, D_MODEL, D_MODEL, D_MODEL, KV_DIM);

    {
        int total = T_SEQ * (D_MODEL / 2) + T_SEQ * (KV_DIM / 2);
        rope_kernel<<<(total + 255) / 256, 256>>>(q, k, cosp, sinp);
    }

    const float scale = 0.08838834764831845f;   // 1/sqrt(128)
    gemm_scores_tf32<<<dim3(T_SEQ / BN, T_SEQ / BM, N_HEADS), blk>>>(q, k, sc, scale);
    softmax_causal<<<N_HEADS * T_SEQ, 256>>>(sc);
    gemm_av_tf32<<<dim3(1, T_SEQ / BM, N_HEADS), blk>>>(sc, v, y);

    gemm_tf32_nt<<<dim3(D_MODEL / BN, T_SEQ / BM), blk>>>(y, wo, out, D_MODEL, D_MODEL, D_MODEL, D_MODEL);
}